// round 1
// baseline (speedup 1.0000x reference)
#include <cuda_runtime.h>
#include <math.h>

// Problem constants
#define BATCH 1024
#define FEAT  512
#define NT    64
#define CSETN 64
#define DDIM  1024   // CSETSIZE * Nrf * Nrf = 64*16

// Output layout (floats): A_real, A_imag, D_real_n, D_imag_n, CSet
#define OFF_AR 0L
#define OFF_AI 4194304L                    // 1024*64*64
#define OFF_DR 8388608L
#define OFF_DI 9437184L                    // + 1024*1024
#define OFF_CS 10485760L                   // + 1024*1024

// Scratch for theta (B x Nt)
__device__ float g_theta[BATCH * NT];

// ---------------------------------------------------------------------------
// SGEMM: C[M,N] = A[M,K] @ W[N,K]^T + bias[N]
// Both operands K-contiguous (NT layout). Optionally two weight matrices
// stacked along N (blockIdx.y selects which), each of width N0.
// ---------------------------------------------------------------------------
template <int BM, int BN, int BK, int TM, int TN>
__global__ __launch_bounds__((BM / TM) * (BN / TN))
void sgemm_bias(const float* __restrict__ A,
                const float* __restrict__ W0, const float* __restrict__ b0,
                const float* __restrict__ W1, const float* __restrict__ b1,
                float* __restrict__ C0, float* __restrict__ C1,
                int K, int N0, int ldC)
{
    constexpr int NTH = (BM / TM) * (BN / TN);
    __shared__ float As[BK][BM + 4];
    __shared__ float Bs[BK][BN + 4];

    const int tid  = threadIdx.x;
    const int tcol = tid % (BN / TN);
    const int trow = tid / (BN / TN);
    const int mBase = blockIdx.x * BM;

    int nBase = blockIdx.y * BN;
    const float* W    = W0;
    const float* bias = b0;
    float*       C    = C0;
    if (nBase >= N0) { W = W1; bias = b1; C = C1; nBase -= N0; }

    float acc[TM][TN];
#pragma unroll
    for (int i = 0; i < TM; i++)
#pragma unroll
        for (int j = 0; j < TN; j++) acc[i][j] = 0.0f;

    for (int k0 = 0; k0 < K; k0 += BK) {
        // Load A tile (BM x BK), store transposed
        for (int i = tid; i < BM * BK / 4; i += NTH) {
            int r  = i / (BK / 4);
            int kc = (i % (BK / 4)) * 4;
            float4 v = *reinterpret_cast<const float4*>(
                &A[(size_t)(mBase + r) * K + k0 + kc]);
            As[kc + 0][r] = v.x; As[kc + 1][r] = v.y;
            As[kc + 2][r] = v.z; As[kc + 3][r] = v.w;
        }
        // Load W tile (BN x BK), store transposed
        for (int i = tid; i < BN * BK / 4; i += NTH) {
            int r  = i / (BK / 4);
            int kc = (i % (BK / 4)) * 4;
            float4 v = *reinterpret_cast<const float4*>(
                &W[(size_t)(nBase + r) * K + k0 + kc]);
            Bs[kc + 0][r] = v.x; Bs[kc + 1][r] = v.y;
            Bs[kc + 2][r] = v.z; Bs[kc + 3][r] = v.w;
        }
        __syncthreads();

#pragma unroll
        for (int k = 0; k < BK; k++) {
            float am[TM], bn[TN];
#pragma unroll
            for (int i = 0; i < TM; i++) am[i] = As[k][trow * TM + i];
#pragma unroll
            for (int j = 0; j < TN; j++) bn[j] = Bs[k][tcol * TN + j];
#pragma unroll
            for (int i = 0; i < TM; i++)
#pragma unroll
                for (int j = 0; j < TN; j++) acc[i][j] += am[i] * bn[j];
        }
        __syncthreads();
    }

    // Epilogue: add bias, write (TN == 4 -> float4 stores)
    const int col = nBase + tcol * TN;
    float4 bv = *reinterpret_cast<const float4*>(&bias[col]);
#pragma unroll
    for (int i = 0; i < TM; i++) {
        int row = mBase + trow * TM + i;
        float4 o;
        o.x = acc[i][0] + bv.x;
        o.y = acc[i][1] + bv.y;
        o.z = acc[i][2] + bv.z;
        o.w = acc[i][3] + bv.w;
        *reinterpret_cast<float4*>(&C[(size_t)row * ldC + col]) = o;
    }
}

// ---------------------------------------------------------------------------
// A_real / A_imag fill: zeros everywhere, cos/sin(theta) on the diagonal.
// One thread per float4 position (per row of 64 -> 16 float4s), both planes.
// ---------------------------------------------------------------------------
__global__ void afill_kernel(const float* __restrict__ theta,
                             float* __restrict__ Ar, float* __restrict__ Ai)
{
    int idx = blockIdx.x * blockDim.x + threadIdx.x;   // [0, BATCH*NT*16)
    if (idx >= BATCH * NT * 16) return;
    int q = idx & 15;          // which float4 within row
    int t = (idx >> 4) & 63;   // row within 64x64 matrix
    int b = idx >> 10;

    float4 zr = make_float4(0.f, 0.f, 0.f, 0.f);
    float4 zi = make_float4(0.f, 0.f, 0.f, 0.f);
    if (q == (t >> 2)) {
        float th = theta[b * NT + t];
        float s, c;
        sincosf(th, &s, &c);
        reinterpret_cast<float*>(&zr)[t & 3] = c;
        reinterpret_cast<float*>(&zi)[t & 3] = s;
    }
    reinterpret_cast<float4*>(Ar)[idx] = zr;
    reinterpret_cast<float4*>(Ai)[idx] = zi;
}

// ---------------------------------------------------------------------------
// D normalization, in place. Per (b, c): scale = 2 / sqrt(8*(|Dr|^2+|Di|^2))
// ---------------------------------------------------------------------------
__global__ void dnorm_kernel(float* __restrict__ Dr, float* __restrict__ Di)
{
    int idx = blockIdx.x * blockDim.x + threadIdx.x;   // [0, BATCH*CSETN)
    if (idx >= BATCH * CSETN) return;
    float4* dr4 = reinterpret_cast<float4*>(Dr) + (size_t)idx * 4;
    float4* di4 = reinterpret_cast<float4*>(Di) + (size_t)idx * 4;

    float4 r[4], m[4];
    float s = 0.f;
#pragma unroll
    for (int k = 0; k < 4; k++) {
        r[k] = dr4[k];
        s += r[k].x * r[k].x + r[k].y * r[k].y + r[k].z * r[k].z + r[k].w * r[k].w;
    }
#pragma unroll
    for (int k = 0; k < 4; k++) {
        m[k] = di4[k];
        s += m[k].x * m[k].x + m[k].y * m[k].y + m[k].z * m[k].z + m[k].w * m[k].w;
    }
    float sc = 2.0f * rsqrtf(8.0f * s);
#pragma unroll
    for (int k = 0; k < 4; k++) {
        float4 o = make_float4(r[k].x * sc, r[k].y * sc, r[k].z * sc, r[k].w * sc);
        dr4[k] = o;
        float4 p = make_float4(m[k].x * sc, m[k].y * sc, m[k].z * sc, m[k].w * sc);
        di4[k] = p;
    }
}

// ---------------------------------------------------------------------------
// CSet passthrough copy (16384 floats)
// ---------------------------------------------------------------------------
__global__ void ccopy_kernel(const float* __restrict__ src, float* __restrict__ dst)
{
    int idx = blockIdx.x * blockDim.x + threadIdx.x;   // float4 index
    if (idx >= CSETN * NT * 4 / 4) return;
    reinterpret_cast<float4*>(dst)[idx] =
        reinterpret_cast<const float4*>(src)[idx];
}

extern "C" void kernel_launch(void* const* d_in, const int* in_sizes, int n_in,
                              void* d_out, int out_size)
{
    const float* x    = (const float*)d_in[0];
    const float* W_A  = (const float*)d_in[1];
    const float* b_A  = (const float*)d_in[2];
    const float* W_Dr = (const float*)d_in[3];
    const float* b_Dr = (const float*)d_in[4];
    const float* W_Di = (const float*)d_in[5];
    const float* b_Di = (const float*)d_in[6];
    const float* CSet = (const float*)d_in[7];
    float* out = (float*)d_out;

    float* theta = nullptr;
    cudaGetSymbolAddress((void**)&theta, g_theta);

    // D_real / D_imag GEMM: M=1024, N=2048 (two stacked 1024-wide matrices), K=512
    {
        dim3 grid(BATCH / 128, (2 * DDIM) / 64);
        sgemm_bias<128, 64, 16, 8, 4><<<grid, 256>>>(
            x, W_Dr, b_Dr, W_Di, b_Di,
            out + OFF_DR, out + OFF_DI, FEAT, DDIM, DDIM);
    }
    // theta GEMM: M=1024, N=64, K=512
    {
        dim3 grid(BATCH / 128, 1);
        sgemm_bias<128, 64, 16, 8, 4><<<grid, 256>>>(
            x, W_A, b_A, nullptr, nullptr,
            theta, nullptr, FEAT, NT, NT);
    }
    // A_real / A_imag diagonal fill
    afill_kernel<<<(BATCH * NT * 16) / 256, 256>>>(theta, out + OFF_AR, out + OFF_AI);
    // D normalization (in place; stream-ordered after the GEMM)
    dnorm_kernel<<<(BATCH * CSETN) / 256, 256>>>(out + OFF_DR, out + OFF_DI);
    // CSet passthrough
    ccopy_kernel<<<(CSETN * NT) / 256, 256>>>(CSet, out + OFF_CS);
}

// round 2
// speedup vs baseline: 1.0893x; 1.0893x over previous
#include <cuda_runtime.h>
#include <math.h>
#include <stdint.h>

#define BATCH 1024
#define FEAT  512
#define NT    64
#define CSETN 64
#define DDIM  1024

// Output layout (floats): A_real, A_imag, D_real_n, D_imag_n, CSet
#define OFF_AR 0L
#define OFF_AI 4194304L
#define OFF_DR 8388608L
#define OFF_DI 9437184L
#define OFF_CS 10485760L

__device__ float g_theta[BATCH * NT];

__device__ __forceinline__ uint32_t f2tf32(float f) {
    uint32_t r;
    asm("cvt.rna.tf32.f32 %0, %1;" : "=r"(r) : "f"(f));
    return r;
}

__device__ __forceinline__ void mma_tf32(float* d, const uint32_t* a, const uint32_t* b) {
    asm volatile(
        "mma.sync.aligned.m16n8k8.row.col.f32.tf32.tf32.f32 "
        "{%0,%1,%2,%3}, {%4,%5,%6,%7}, {%8,%9}, {%0,%1,%2,%3};"
        : "+f"(d[0]), "+f"(d[1]), "+f"(d[2]), "+f"(d[3])
        : "r"(a[0]), "r"(a[1]), "r"(a[2]), "r"(a[3]), "r"(b[0]), "r"(b[1]));
}

// ---------------------------------------------------------------------------
// tf32 tensor-core GEMM: C[M,N] = A[M,K] @ W[N,K]^T + bias[N]
// Two weight matrices stacked along grid.y (Dr then Di), each DDIM wide.
// BM=128, BN=128, BK=16, 256 threads = 8 warps (2 along M x 4 along N),
// warp tile 64x32 (4 m16 x 4 n8 mma tiles), double-buffered smem.
// ---------------------------------------------------------------------------
__global__ __launch_bounds__(256)
void mma_gemm(const float* __restrict__ A,
              const float* __restrict__ W0, const float* __restrict__ b0,
              const float* __restrict__ W1, const float* __restrict__ b1,
              float* __restrict__ C0, float* __restrict__ C1)
{
    constexpr int BM = 128, BN = 128, BK = 16;
    constexpr int LDA = BM + 1;
    constexpr int LDB = BN + 1;
    constexpr int NKT = FEAT / BK;          // 32 k-tiles

    __shared__ uint32_t As[2][BK * LDA];
    __shared__ uint32_t Bs[2][BK * LDB];

    const int tid   = threadIdx.x;
    const int lane  = tid & 31;
    const int warp  = tid >> 5;
    const int g     = lane >> 2;            // 0..7
    const int t4    = lane & 3;             // 0..3
    const int warpM = warp & 1;             // 0..1
    const int warpN = warp >> 1;            // 0..3

    const int mBase = blockIdx.x * BM;
    int nBase = blockIdx.y * BN;
    const float* W    = W0;
    const float* bias = b0;
    float*       C    = C0;
    if (nBase >= DDIM) { W = W1; bias = b1; C = C1; nBase -= DDIM; }

    // global loaders: each thread loads 2 float4 per matrix per tile
    const int lr = tid >> 2;                // 0..63
    const int lk = (tid & 3) * 4;           // 0,4,8,12

    const float* Aptr = A + (size_t)(mBase + lr) * FEAT + lk;
    const float* Wptr = W + (size_t)(nBase + lr) * FEAT + lk;

    float d[4][4][4];
#pragma unroll
    for (int i = 0; i < 4; i++)
#pragma unroll
        for (int j = 0; j < 4; j++)
#pragma unroll
            for (int v = 0; v < 4; v++) d[i][j][v] = 0.0f;

    float4 pa0, pa1, pb0, pb1;

#define LOADG(kt)                                                          \
    do {                                                                   \
        const float* ap = Aptr + (kt) * BK;                                \
        const float* wp = Wptr + (kt) * BK;                                \
        pa0 = *reinterpret_cast<const float4*>(ap);                        \
        pa1 = *reinterpret_cast<const float4*>(ap + 64 * FEAT);            \
        pb0 = *reinterpret_cast<const float4*>(wp);                        \
        pb1 = *reinterpret_cast<const float4*>(wp + 64 * FEAT);            \
    } while (0)

#define STS(bf)                                                            \
    do {                                                                   \
        As[bf][(lk + 0) * LDA + lr]      = f2tf32(pa0.x);                  \
        As[bf][(lk + 1) * LDA + lr]      = f2tf32(pa0.y);                  \
        As[bf][(lk + 2) * LDA + lr]      = f2tf32(pa0.z);                  \
        As[bf][(lk + 3) * LDA + lr]      = f2tf32(pa0.w);                  \
        As[bf][(lk + 0) * LDA + lr + 64] = f2tf32(pa1.x);                  \
        As[bf][(lk + 1) * LDA + lr + 64] = f2tf32(pa1.y);                  \
        As[bf][(lk + 2) * LDA + lr + 64] = f2tf32(pa1.z);                  \
        As[bf][(lk + 3) * LDA + lr + 64] = f2tf32(pa1.w);                  \
        Bs[bf][(lk + 0) * LDB + lr]      = f2tf32(pb0.x);                  \
        Bs[bf][(lk + 1) * LDB + lr]      = f2tf32(pb0.y);                  \
        Bs[bf][(lk + 2) * LDB + lr]      = f2tf32(pb0.z);                  \
        Bs[bf][(lk + 3) * LDB + lr]      = f2tf32(pb0.w);                  \
        Bs[bf][(lk + 0) * LDB + lr + 64] = f2tf32(pb1.x);                  \
        Bs[bf][(lk + 1) * LDB + lr + 64] = f2tf32(pb1.y);                  \
        Bs[bf][(lk + 2) * LDB + lr + 64] = f2tf32(pb1.z);                  \
        Bs[bf][(lk + 3) * LDB + lr + 64] = f2tf32(pb1.w);                  \
    } while (0)

    LOADG(0);
    STS(0);
    __syncthreads();

    int buf = 0;
    for (int kt = 0; kt < NKT; kt++) {
        if (kt < NKT - 1) LOADG(kt + 1);

        const uint32_t* as = As[buf];
        const uint32_t* bs = Bs[buf];
#pragma unroll
        for (int ks = 0; ks < 2; ks++) {
            uint32_t af[4][4];
#pragma unroll
            for (int mi = 0; mi < 4; mi++) {
                int m = warpM * 64 + mi * 16 + g;
                af[mi][0] = as[(ks * 8 + t4) * LDA + m];
                af[mi][1] = as[(ks * 8 + t4) * LDA + m + 8];
                af[mi][2] = as[(ks * 8 + t4 + 4) * LDA + m];
                af[mi][3] = as[(ks * 8 + t4 + 4) * LDA + m + 8];
            }
            uint32_t bfq[4][2];
#pragma unroll
            for (int nj = 0; nj < 4; nj++) {
                int n = warpN * 32 + nj * 8 + g;
                bfq[nj][0] = bs[(ks * 8 + t4) * LDB + n];
                bfq[nj][1] = bs[(ks * 8 + t4 + 4) * LDB + n];
            }
#pragma unroll
            for (int mi = 0; mi < 4; mi++)
#pragma unroll
                for (int nj = 0; nj < 4; nj++)
                    mma_tf32(d[mi][nj], af[mi], bfq[nj]);
        }

        if (kt < NKT - 1) {
            STS(buf ^ 1);
            __syncthreads();
            buf ^= 1;
        }
    }

    // Epilogue: add bias, write float2 pairs
#pragma unroll
    for (int nj = 0; nj < 4; nj++) {
        int col = nBase + warpN * 32 + nj * 8 + 2 * t4;
        float bx = bias[col];
        float by = bias[col + 1];
#pragma unroll
        for (int mi = 0; mi < 4; mi++) {
            int row = mBase + warpM * 64 + mi * 16 + g;
            float2 o0 = make_float2(d[mi][nj][0] + bx, d[mi][nj][1] + by);
            float2 o1 = make_float2(d[mi][nj][2] + bx, d[mi][nj][3] + by);
            *reinterpret_cast<float2*>(&C[(size_t)row * DDIM + col]) = o0;
            *reinterpret_cast<float2*>(&C[(size_t)(row + 8) * DDIM + col]) = o1;
        }
    }
#undef LOADG
#undef STS
}

// ---------------------------------------------------------------------------
// SIMT SGEMM for theta (small N): C[M,N] = A[M,K] @ W[N,K]^T + bias
// ---------------------------------------------------------------------------
template <int BM, int BN, int BK, int TM, int TN>
__global__ __launch_bounds__((BM / TM) * (BN / TN))
void sgemm_bias(const float* __restrict__ A,
                const float* __restrict__ W, const float* __restrict__ bias,
                float* __restrict__ C, int K, int ldC)
{
    constexpr int NTH = (BM / TM) * (BN / TN);
    __shared__ float As[BK][BM + 4];
    __shared__ float Bs[BK][BN + 4];

    const int tid  = threadIdx.x;
    const int tcol = tid % (BN / TN);
    const int trow = tid / (BN / TN);
    const int mBase = blockIdx.x * BM;
    const int nBase = blockIdx.y * BN;

    float acc[TM][TN];
#pragma unroll
    for (int i = 0; i < TM; i++)
#pragma unroll
        for (int j = 0; j < TN; j++) acc[i][j] = 0.0f;

    for (int k0 = 0; k0 < K; k0 += BK) {
        for (int i = tid; i < BM * BK / 4; i += NTH) {
            int r  = i / (BK / 4);
            int kc = (i % (BK / 4)) * 4;
            float4 v = *reinterpret_cast<const float4*>(
                &A[(size_t)(mBase + r) * K + k0 + kc]);
            As[kc + 0][r] = v.x; As[kc + 1][r] = v.y;
            As[kc + 2][r] = v.z; As[kc + 3][r] = v.w;
        }
        for (int i = tid; i < BN * BK / 4; i += NTH) {
            int r  = i / (BK / 4);
            int kc = (i % (BK / 4)) * 4;
            float4 v = *reinterpret_cast<const float4*>(
                &W[(size_t)(nBase + r) * K + k0 + kc]);
            Bs[kc + 0][r] = v.x; Bs[kc + 1][r] = v.y;
            Bs[kc + 2][r] = v.z; Bs[kc + 3][r] = v.w;
        }
        __syncthreads();

#pragma unroll
        for (int k = 0; k < BK; k++) {
            float am[TM], bn[TN];
#pragma unroll
            for (int i = 0; i < TM; i++) am[i] = As[k][trow * TM + i];
#pragma unroll
            for (int j = 0; j < TN; j++) bn[j] = Bs[k][tcol * TN + j];
#pragma unroll
            for (int i = 0; i < TM; i++)
#pragma unroll
                for (int j = 0; j < TN; j++) acc[i][j] += am[i] * bn[j];
        }
        __syncthreads();
    }

    const int col = nBase + tcol * TN;
    float4 bv = *reinterpret_cast<const float4*>(&bias[col]);
#pragma unroll
    for (int i = 0; i < TM; i++) {
        int row = mBase + trow * TM + i;
        float4 o;
        o.x = acc[i][0] + bv.x;
        o.y = acc[i][1] + bv.y;
        o.z = acc[i][2] + bv.z;
        o.w = acc[i][3] + bv.w;
        *reinterpret_cast<float4*>(&C[(size_t)row * ldC + col]) = o;
    }
}

// ---------------------------------------------------------------------------
// A_real / A_imag: zeros + cos/sin(theta) on the diagonal.
// ---------------------------------------------------------------------------
__global__ void afill_kernel(const float* __restrict__ theta,
                             float* __restrict__ Ar, float* __restrict__ Ai)
{
    int idx = blockIdx.x * blockDim.x + threadIdx.x;
    if (idx >= BATCH * NT * 16) return;
    int q = idx & 15;
    int t = (idx >> 4) & 63;
    int b = idx >> 10;

    float4 zr = make_float4(0.f, 0.f, 0.f, 0.f);
    float4 zi = make_float4(0.f, 0.f, 0.f, 0.f);
    if (q == (t >> 2)) {
        float th = theta[b * NT + t];
        float s, c;
        sincosf(th, &s, &c);
        reinterpret_cast<float*>(&zr)[t & 3] = c;
        reinterpret_cast<float*>(&zi)[t & 3] = s;
    }
    reinterpret_cast<float4*>(Ar)[idx] = zr;
    reinterpret_cast<float4*>(Ai)[idx] = zi;
}

// ---------------------------------------------------------------------------
// D normalization: 4 threads per (b,c), shuffle reduction, coalesced.
// scale = sqrt(Nrf) / sqrt(Nk * sum(Dr^2 + Di^2)) = 2 * rsqrt(8 * s)
// ---------------------------------------------------------------------------
__global__ void dnorm_kernel(float* __restrict__ Dr, float* __restrict__ Di)
{
    int tid = blockIdx.x * blockDim.x + threadIdx.x;   // [0, BATCH*CSETN*4)
    if (tid >= BATCH * CSETN * 4) return;

    float4 r = reinterpret_cast<float4*>(Dr)[tid];
    float4 m = reinterpret_cast<float4*>(Di)[tid];
    float s = r.x * r.x + r.y * r.y + r.z * r.z + r.w * r.w
            + m.x * m.x + m.y * m.y + m.z * m.z + m.w * m.w;
    s += __shfl_xor_sync(0xffffffffu, s, 1);
    s += __shfl_xor_sync(0xffffffffu, s, 2);
    float sc = 2.0f * rsqrtf(8.0f * s);

    reinterpret_cast<float4*>(Dr)[tid] =
        make_float4(r.x * sc, r.y * sc, r.z * sc, r.w * sc);
    reinterpret_cast<float4*>(Di)[tid] =
        make_float4(m.x * sc, m.y * sc, m.z * sc, m.w * sc);
}

__global__ void ccopy_kernel(const float* __restrict__ src, float* __restrict__ dst)
{
    int idx = blockIdx.x * blockDim.x + threadIdx.x;
    if (idx >= CSETN * NT) return;
    reinterpret_cast<float4*>(dst)[idx] =
        reinterpret_cast<const float4*>(src)[idx];
}

extern "C" void kernel_launch(void* const* d_in, const int* in_sizes, int n_in,
                              void* d_out, int out_size)
{
    const float* x    = (const float*)d_in[0];
    const float* W_A  = (const float*)d_in[1];
    const float* b_A  = (const float*)d_in[2];
    const float* W_Dr = (const float*)d_in[3];
    const float* b_Dr = (const float*)d_in[4];
    const float* W_Di = (const float*)d_in[5];
    const float* b_Di = (const float*)d_in[6];
    const float* CSet = (const float*)d_in[7];
    float* out = (float*)d_out;

    float* theta = nullptr;
    cudaGetSymbolAddress((void**)&theta, g_theta);

    // D_real / D_imag tensor-core GEMM: M=1024, N=2*1024, K=512
    {
        dim3 grid(BATCH / 128, (2 * DDIM) / 128);
        mma_gemm<<<grid, 256>>>(x, W_Dr, b_Dr, W_Di, b_Di,
                                out + OFF_DR, out + OFF_DI);
    }
    // theta GEMM: M=1024, N=64, K=512 (SIMT, 16 blocks)
    {
        dim3 grid(BATCH / 64, 1);
        sgemm_bias<64, 64, 16, 4, 4><<<grid, 256>>>(
            x, W_A, b_A, theta, FEAT, NT);
    }
    // A_real / A_imag diagonal fill
    afill_kernel<<<(BATCH * NT * 16) / 256, 256>>>(theta, out + OFF_AR, out + OFF_AI);
    // D normalization
    dnorm_kernel<<<(BATCH * CSETN * 4) / 256, 256>>>(out + OFF_DR, out + OFF_DI);
    // CSet passthrough
    ccopy_kernel<<<(CSETN * NT + 255) / 256, 256>>>(CSet, out + OFF_CS);
}

// round 3
// speedup vs baseline: 2.2096x; 2.0285x over previous
#include <cuda_runtime.h>
#include <math.h>
#include <stdint.h>

#define BATCH 1024
#define FEAT  512
#define NT    64
#define CSETN 64
#define DDIM  1024

// Output layout (floats): A_real, A_imag, D_real_n, D_imag_n, CSet
#define OFF_AR 0L
#define OFF_AI 4194304L
#define OFF_DR 8388608L
#define OFF_DI 9437184L
#define OFF_CS 10485760L

__device__ float g_theta[BATCH * NT];

__device__ __forceinline__ uint32_t f2tf32(float f) {
    uint32_t r;
    asm("cvt.rna.tf32.f32 %0, %1;" : "=r"(r) : "f"(f));
    return r;
}

__device__ __forceinline__ void mma_tf32(float* d, const uint32_t* a, const uint32_t* b) {
    asm volatile(
        "mma.sync.aligned.m16n8k8.row.col.f32.tf32.tf32.f32 "
        "{%0,%1,%2,%3}, {%4,%5,%6,%7}, {%8,%9}, {%0,%1,%2,%3};"
        : "+f"(d[0]), "+f"(d[1]), "+f"(d[2]), "+f"(d[3])
        : "r"(a[0]), "r"(a[1]), "r"(a[2]), "r"(a[3]), "r"(b[0]), "r"(b[1]));
}

// ---------------------------------------------------------------------------
// Fused tf32 GEMM + normalization.
// Each CTA: rows mBase..mBase+127 of batch, cols n0..n0+63 of BOTH Dr and Di.
// B smem rows 0..63 = W_Dr[n0..], rows 64..127 = W_Di[n0..].
// 8 warps: warpM in {0,1} (64 rows), warpN in {0..3}:
//   warpN 0,1 -> Dr cols (warpN&1)*32.. ; warpN 2,3 -> Di cols.
// smem layout [m][k], LDK=20: fragment LDS fully bank-conflict-free.
// Epilogue computes per-(row,cset) norm across Dr+Di and writes normalized D.
// ---------------------------------------------------------------------------
__global__ __launch_bounds__(256)
void mma_gemm_fused(const float* __restrict__ A,
                    const float* __restrict__ Wr, const float* __restrict__ br,
                    const float* __restrict__ Wi, const float* __restrict__ bi,
                    float* __restrict__ Cr, float* __restrict__ Ci)
{
    constexpr int BK  = 16;
    constexpr int LDK = 20;
    constexpr int NKT = FEAT / BK;          // 32

    __shared__ uint32_t As[2][128 * LDK];
    __shared__ uint32_t Bs[2][128 * LDK];
    __shared__ float    P[2][128][4];       // [Dr/Di][row][local cset]

    const int tid   = threadIdx.x;
    const int lane  = tid & 31;
    const int warp  = tid >> 5;
    const int g     = lane >> 2;            // 0..7
    const int t4    = lane & 3;             // 0..3
    const int warpM = warp & 1;
    const int warpN = warp >> 1;            // 0..3

    const int mBase = blockIdx.x * 128;
    const int n0    = blockIdx.y * 64;

    const int lr = tid >> 2;                // 0..63
    const int lk = (tid & 3) * 4;           // 0,4,8,12

    const float* Ap  = A  + (size_t)(mBase + lr) * FEAT + lk;
    const float* Wrp = Wr + (size_t)(n0 + lr) * FEAT + lk;
    const float* Wip = Wi + (size_t)(n0 + lr) * FEAT + lk;

    float d[4][4][4];
#pragma unroll
    for (int i = 0; i < 4; i++)
#pragma unroll
        for (int j = 0; j < 4; j++)
#pragma unroll
            for (int v = 0; v < 4; v++) d[i][j][v] = 0.0f;

    float4 pa0, pa1, pb0, pb1;

#define LOADG(kt)                                                            \
    do {                                                                     \
        pa0 = *reinterpret_cast<const float4*>(Ap  + (kt) * BK);             \
        pa1 = *reinterpret_cast<const float4*>(Ap  + (kt) * BK + 64 * FEAT); \
        pb0 = *reinterpret_cast<const float4*>(Wrp + (kt) * BK);             \
        pb1 = *reinterpret_cast<const float4*>(Wip + (kt) * BK);             \
    } while (0)

#define STS(bf)                                                              \
    do {                                                                     \
        *reinterpret_cast<uint4*>(&As[bf][lr * LDK + lk]) =                  \
            make_uint4(f2tf32(pa0.x), f2tf32(pa0.y), f2tf32(pa0.z), f2tf32(pa0.w)); \
        *reinterpret_cast<uint4*>(&As[bf][(lr + 64) * LDK + lk]) =           \
            make_uint4(f2tf32(pa1.x), f2tf32(pa1.y), f2tf32(pa1.z), f2tf32(pa1.w)); \
        *reinterpret_cast<uint4*>(&Bs[bf][lr * LDK + lk]) =                  \
            make_uint4(f2tf32(pb0.x), f2tf32(pb0.y), f2tf32(pb0.z), f2tf32(pb0.w)); \
        *reinterpret_cast<uint4*>(&Bs[bf][(lr + 64) * LDK + lk]) =           \
            make_uint4(f2tf32(pb1.x), f2tf32(pb1.y), f2tf32(pb1.z), f2tf32(pb1.w)); \
    } while (0)

    LOADG(0);
    STS(0);
    __syncthreads();

    int buf = 0;
    for (int kt = 0; kt < NKT; kt++) {
        if (kt < NKT - 1) LOADG(kt + 1);

        const uint32_t* as = As[buf];
        const uint32_t* bs = Bs[buf];
#pragma unroll
        for (int ks = 0; ks < 2; ks++) {
            const int kb = ks * 8 + t4;
            uint32_t af[4][4];
#pragma unroll
            for (int mi = 0; mi < 4; mi++) {
                const int r0 = (warpM * 64 + mi * 16 + g) * LDK;
                af[mi][0] = as[r0 + kb];
                af[mi][1] = as[r0 + 8 * LDK + kb];
                af[mi][2] = as[r0 + kb + 4];
                af[mi][3] = as[r0 + 8 * LDK + kb + 4];
            }
            uint32_t bq[4][2];
#pragma unroll
            for (int nj = 0; nj < 4; nj++) {
                const int rb = (warpN * 32 + nj * 8 + g) * LDK;
                bq[nj][0] = bs[rb + kb];
                bq[nj][1] = bs[rb + kb + 4];
            }
#pragma unroll
            for (int mi = 0; mi < 4; mi++)
#pragma unroll
                for (int nj = 0; nj < 4; nj++)
                    mma_tf32(d[mi][nj], af[mi], bq[nj]);
        }

        if (kt < NKT - 1) {
            STS(buf ^ 1);
            __syncthreads();
            buf ^= 1;
        }
    }
#undef LOADG
#undef STS

    // ---------------- Epilogue: bias + fused normalization ----------------
    const bool  isDi = (warpN >= 2);
    const int   nloc = (warpN & 1) * 32;
    const float* bsrc = isDi ? bi : br;

#pragma unroll
    for (int nj = 0; nj < 4; nj++) {
        int col = n0 + nloc + nj * 8 + 2 * t4;
        float bx = bsrc[col];
        float by = bsrc[col + 1];
#pragma unroll
        for (int mi = 0; mi < 4; mi++) {
            d[mi][nj][0] += bx; d[mi][nj][1] += by;
            d[mi][nj][2] += bx; d[mi][nj][3] += by;
        }
    }

    // Partial squared sums: per (mi, row-half, nj-pair)
    float s[4][2][2];
#pragma unroll
    for (int mi = 0; mi < 4; mi++)
#pragma unroll
        for (int rv = 0; rv < 2; rv++)
#pragma unroll
            for (int p = 0; p < 2; p++) s[mi][rv][p] = 0.0f;

#pragma unroll
    for (int mi = 0; mi < 4; mi++)
#pragma unroll
        for (int nj = 0; nj < 4; nj++) {
            int p = nj >> 1;
            s[mi][0][p] += d[mi][nj][0] * d[mi][nj][0] + d[mi][nj][1] * d[mi][nj][1];
            s[mi][1][p] += d[mi][nj][2] * d[mi][nj][2] + d[mi][nj][3] * d[mi][nj][3];
        }

#pragma unroll
    for (int mi = 0; mi < 4; mi++)
#pragma unroll
        for (int rv = 0; rv < 2; rv++)
#pragma unroll
            for (int p = 0; p < 2; p++) {
                float v = s[mi][rv][p];
                v += __shfl_xor_sync(0xffffffffu, v, 1);
                v += __shfl_xor_sync(0xffffffffu, v, 2);
                s[mi][rv][p] = v;
            }

    const int ri = warpN >> 1;
    if (t4 == 0) {
#pragma unroll
        for (int mi = 0; mi < 4; mi++)
#pragma unroll
            for (int rv = 0; rv < 2; rv++)
#pragma unroll
                for (int p = 0; p < 2; p++)
                    P[ri][warpM * 64 + mi * 16 + g + 8 * rv][(warpN & 1) * 2 + p]
                        = s[mi][rv][p];
    }
    __syncthreads();

    float* Cout = isDi ? Ci : Cr;
#pragma unroll
    for (int mi = 0; mi < 4; mi++)
#pragma unroll
        for (int rv = 0; rv < 2; rv++) {
            int row  = warpM * 64 + mi * 16 + g + 8 * rv;
            int grow = mBase + row;
#pragma unroll
            for (int p = 0; p < 2; p++) {
                int cs = (warpN & 1) * 2 + p;
                float tot = P[0][row][cs] + P[1][row][cs];
                float sc  = 2.0f * rsqrtf(8.0f * tot);
#pragma unroll
                for (int q = 0; q < 2; q++) {
                    int nj  = 2 * p + q;
                    int col = n0 + nloc + nj * 8 + 2 * t4;
                    float v0 = d[mi][nj][rv * 2 + 0] * sc;
                    float v1 = d[mi][nj][rv * 2 + 1] * sc;
                    *reinterpret_cast<float2*>(&Cout[(size_t)grow * DDIM + col]) =
                        make_float2(v0, v1);
                }
            }
        }
}

// ---------------------------------------------------------------------------
// SIMT SGEMM for theta: C[M,64] = A[M,512] @ W[64,512]^T + bias
// ---------------------------------------------------------------------------
template <int BM, int BN, int BK, int TM, int TN>
__global__ __launch_bounds__((BM / TM) * (BN / TN))
void sgemm_bias(const float* __restrict__ A,
                const float* __restrict__ W, const float* __restrict__ bias,
                float* __restrict__ C, int K, int ldC)
{
    constexpr int NTH = (BM / TM) * (BN / TN);
    __shared__ float As[BK][BM + 4];
    __shared__ float Bs[BK][BN + 4];

    const int tid  = threadIdx.x;
    const int tcol = tid % (BN / TN);
    const int trow = tid / (BN / TN);
    const int mBase = blockIdx.x * BM;
    const int nBase = blockIdx.y * BN;

    float acc[TM][TN];
#pragma unroll
    for (int i = 0; i < TM; i++)
#pragma unroll
        for (int j = 0; j < TN; j++) acc[i][j] = 0.0f;

    for (int k0 = 0; k0 < K; k0 += BK) {
        for (int i = tid; i < BM * BK / 4; i += NTH) {
            int r  = i / (BK / 4);
            int kc = (i % (BK / 4)) * 4;
            float4 v = *reinterpret_cast<const float4*>(
                &A[(size_t)(mBase + r) * K + k0 + kc]);
            As[kc + 0][r] = v.x; As[kc + 1][r] = v.y;
            As[kc + 2][r] = v.z; As[kc + 3][r] = v.w;
        }
        for (int i = tid; i < BN * BK / 4; i += NTH) {
            int r  = i / (BK / 4);
            int kc = (i % (BK / 4)) * 4;
            float4 v = *reinterpret_cast<const float4*>(
                &W[(size_t)(nBase + r) * K + k0 + kc]);
            Bs[kc + 0][r] = v.x; Bs[kc + 1][r] = v.y;
            Bs[kc + 2][r] = v.z; Bs[kc + 3][r] = v.w;
        }
        __syncthreads();

#pragma unroll
        for (int k = 0; k < BK; k++) {
            float am[TM], bn[TN];
#pragma unroll
            for (int i = 0; i < TM; i++) am[i] = As[k][trow * TM + i];
#pragma unroll
            for (int j = 0; j < TN; j++) bn[j] = Bs[k][tcol * TN + j];
#pragma unroll
            for (int i = 0; i < TM; i++)
#pragma unroll
                for (int j = 0; j < TN; j++) acc[i][j] += am[i] * bn[j];
        }
        __syncthreads();
    }

    const int col = nBase + tcol * TN;
    float4 bv = *reinterpret_cast<const float4*>(&bias[col]);
#pragma unroll
    for (int i = 0; i < TM; i++) {
        int row = mBase + trow * TM + i;
        float4 o;
        o.x = acc[i][0] + bv.x;
        o.y = acc[i][1] + bv.y;
        o.z = acc[i][2] + bv.z;
        o.w = acc[i][3] + bv.w;
        *reinterpret_cast<float4*>(&C[(size_t)row * ldC + col]) = o;
    }
}

// ---------------------------------------------------------------------------
// A_real / A_imag zeros + diag(cos/sin) fill; tail blocks copy CSet.
// ---------------------------------------------------------------------------
__global__ void afill_kernel(const float* __restrict__ theta,
                             float* __restrict__ Ar, float* __restrict__ Ai,
                             const float* __restrict__ csrc,
                             float* __restrict__ cdst)
{
    int idx = blockIdx.x * blockDim.x + threadIdx.x;
    if (idx < BATCH * NT * 16) {
        int q = idx & 15;
        int t = (idx >> 4) & 63;
        int b = idx >> 10;

        float4 zr = make_float4(0.f, 0.f, 0.f, 0.f);
        float4 zi = make_float4(0.f, 0.f, 0.f, 0.f);
        if (q == (t >> 2)) {
            float th = theta[b * NT + t];
            float s, c;
            sincosf(th, &s, &c);
            reinterpret_cast<float*>(&zr)[t & 3] = c;
            reinterpret_cast<float*>(&zi)[t & 3] = s;
        }
        reinterpret_cast<float4*>(Ar)[idx] = zr;
        reinterpret_cast<float4*>(Ai)[idx] = zi;
    } else {
        int c = idx - BATCH * NT * 16;
        if (c < CSETN * NT) {
            reinterpret_cast<float4*>(cdst)[c] =
                reinterpret_cast<const float4*>(csrc)[c];
        }
    }
}

extern "C" void kernel_launch(void* const* d_in, const int* in_sizes, int n_in,
                              void* d_out, int out_size)
{
    const float* x    = (const float*)d_in[0];
    const float* W_A  = (const float*)d_in[1];
    const float* b_A  = (const float*)d_in[2];
    const float* W_Dr = (const float*)d_in[3];
    const float* b_Dr = (const float*)d_in[4];
    const float* W_Di = (const float*)d_in[5];
    const float* b_Di = (const float*)d_in[6];
    const float* CSet = (const float*)d_in[7];
    float* out = (float*)d_out;

    float* theta = nullptr;
    cudaGetSymbolAddress((void**)&theta, g_theta);

    // Fused D GEMM + normalization: 128 CTAs
    {
        dim3 grid(BATCH / 128, DDIM / 64);
        mma_gemm_fused<<<grid, 256>>>(x, W_Dr, b_Dr, W_Di, b_Di,
                                      out + OFF_DR, out + OFF_DI);
    }
    // theta GEMM
    {
        dim3 grid(BATCH / 64, 1);
        sgemm_bias<64, 64, 16, 4, 4><<<grid, 256>>>(
            x, W_A, b_A, theta, FEAT, NT);
    }
    // A fill + CSet copy (tail blocks)
    {
        int main_threads = BATCH * NT * 16;          // 1M float4 slots
        int tail_threads = CSETN * NT;               // 4096 float4 copies
        int total = main_threads + tail_threads;
        afill_kernel<<<(total + 255) / 256, 256>>>(
            theta, out + OFF_AR, out + OFF_AI, CSet, out + OFF_CS);
    }
}